// round 11
// baseline (speedup 1.0000x reference)
#include <cuda_runtime.h>
#include <cuda_fp16.h>
#include <math.h>
#include <stdint.h>

// Inputs:
// 0 hidden_states f32 [2,2048,1024]
// 1 attention_mask f32 [2,1,1,2048]
// 2 local_attention_mask i32 [2,1,2048,2048]
// 3 gate_outputs f32 [2,16,2048,1]
// 4 Wq 5 bq 6 Wk 7 bk 8 Wv 9 bv
// out f32 [2,2048,1024]

#define B_  2
#define S_  2048
#define H_  1024
#define NH_ 16
#define DH_ 64
#define SCALE_Q 0.18033688011112042f   // 0.125 * log2(e)

// fp16 scratch (device globals; no allocation allowed)
__device__ __half g_xh[(size_t)B_*S_*H_];
__device__ __half g_wh[3][(size_t)H_*H_];
__device__ __half g_qh[(size_t)B_*NH_*S_*DH_];
__device__ __half g_kh[(size_t)B_*NH_*S_*DH_];
__device__ __half g_vh[(size_t)B_*NH_*S_*DH_];
__device__ unsigned long long g_lm[(size_t)B_*S_*32];   // bit-packed local mask

// ===================== helpers =====================
__device__ __forceinline__ uint32_t smem_u32(const void* p) {
    uint32_t a;
    asm("{ .reg .u64 t; cvta.to.shared.u64 t, %1; cvt.u32.u64 %0, t; }" : "=r"(a) : "l"(p));
    return a;
}
// pack two f32 -> f16x2 (lo=a, hi=b)
__device__ __forceinline__ uint32_t pack2(float a, float b) {
    uint32_t h;
    asm("cvt.rn.f16x2.f32 %0, %1, %2;" : "=r"(h) : "f"(b), "f"(a));
    return h;
}
__device__ __forceinline__ uint32_t hex2(uint32_t x) {
    uint32_t y; asm("ex2.approx.f16x2 %0, %1;" : "=r"(y) : "r"(x)); return y;
}
__device__ __forceinline__ uint32_t hmul2(uint32_t a, uint32_t b) {
    uint32_t d; asm("mul.f16x2 %0, %1, %2;" : "=r"(d) : "r"(a), "r"(b)); return d;
}
__device__ __forceinline__ uint32_t hadd2(uint32_t a, uint32_t b) {
    uint32_t d; asm("add.f16x2 %0, %1, %2;" : "=r"(d) : "r"(a), "r"(b)); return d;
}
__device__ __forceinline__ float2 h2f2(uint32_t h) {
    __half2 v = *(__half2*)&h;
    return __half22float2(v);
}
__device__ __forceinline__ void ldsm_x4(uint32_t* r, uint32_t a) {
    asm volatile("ldmatrix.sync.aligned.m8n8.x4.shared.b16 {%0,%1,%2,%3}, [%4];"
        : "=r"(r[0]), "=r"(r[1]), "=r"(r[2]), "=r"(r[3]) : "r"(a));
}
__device__ __forceinline__ void ldsm_x4t(uint32_t* r, uint32_t a) {
    asm volatile("ldmatrix.sync.aligned.m8n8.x4.trans.shared.b16 {%0,%1,%2,%3}, [%4];"
        : "=r"(r[0]), "=r"(r[1]), "=r"(r[2]), "=r"(r[3]) : "r"(a));
}
// fp32-accumulate mma (half rate)
__device__ __forceinline__ void mma16816(float* c, const uint32_t* a, const uint32_t* b) {
    asm volatile("mma.sync.aligned.m16n8k16.row.col.f32.f16.f16.f32 "
        "{%0,%1,%2,%3}, {%4,%5,%6,%7}, {%8,%9}, {%0,%1,%2,%3};"
        : "+f"(c[0]), "+f"(c[1]), "+f"(c[2]), "+f"(c[3])
        : "r"(a[0]), "r"(a[1]), "r"(a[2]), "r"(a[3]), "r"(b[0]), "r"(b[1]));
}
// fp16-accumulate mma (full rate) — D/C are 2 f16x2 regs
__device__ __forceinline__ void mma16816h(uint32_t* c, const uint32_t* a, const uint32_t* b) {
    asm volatile("mma.sync.aligned.m16n8k16.row.col.f16.f16.f16.f16 "
        "{%0,%1}, {%2,%3,%4,%5}, {%6,%7}, {%0,%1};"
        : "+r"(c[0]), "+r"(c[1])
        : "r"(a[0]), "r"(a[1]), "r"(a[2]), "r"(a[3]), "r"(b[0]), "r"(b[1]));
}
#define CPASYNC(dst, src) \
    asm volatile("cp.async.cg.shared.global [%0], [%1], 16;" :: "r"(dst), "l"(src))
#define CPCOMMIT() asm volatile("cp.async.commit_group;" ::: "memory")
#define CPWAIT(n)  asm volatile("cp.async.wait_group %0;" :: "n"(n) : "memory")

// ---------------------------------------------------------------------------
// prep: bit-pack local mask  +  fp32->fp16 convert of X, Wq, Wk, Wv (1 launch)
// ---------------------------------------------------------------------------
#define MBLK 512                       // B_*S_*32 / 256
#define XN4 (B_*S_*H_/4)
#define WN4 (H_*H_/4)
__global__ __launch_bounds__(256) void prep(
    const int* __restrict__ lmask,
    const float4* __restrict__ X,  const float4* __restrict__ Wq,
    const float4* __restrict__ Wk, const float4* __restrict__ Wv)
{
    const int blk = blockIdx.x;
    if (blk < MBLK) {
        const int i = blk * 256 + threadIdx.x;     // 0 .. B*S*32-1
        const int row = i >> 5, seg = i & 31;
        const int4* p = (const int4*)(lmask + ((size_t)row << 11) + seg * 64);
        unsigned long long m = 0ull;
        #pragma unroll
        for (int u = 0; u < 16; u++) {
            int4 v = p[u];
            m |= ((unsigned long long)(v.x != 0)) << (u*4 + 0);
            m |= ((unsigned long long)(v.y != 0)) << (u*4 + 1);
            m |= ((unsigned long long)(v.z != 0)) << (u*4 + 2);
            m |= ((unsigned long long)(v.w != 0)) << (u*4 + 3);
        }
        g_lm[i] = m;
        return;
    }
    int i = (blk - MBLK) * 256 + threadIdx.x;
    const float4* src;
    uint2* dst;
    if (i < XN4)              { src = X;  dst = (uint2*)g_xh;    }
    else if (i < XN4 + WN4)   { src = Wq; dst = (uint2*)g_wh[0]; i -= XN4; }
    else if (i < XN4 + 2*WN4) { src = Wk; dst = (uint2*)g_wh[1]; i -= XN4 + WN4; }
    else                      { src = Wv; dst = (uint2*)g_wh[2]; i -= XN4 + 2*WN4; }
    float4 f = src[i];
    dst[i] = make_uint2(pack2(f.x, f.y), pack2(f.z, f.w));
}

// ---------------------------------------------------------------------------
// QKV projection via fp16 HMMA with fp16-accumulate + segmented fp32
// promotion (every k=64):  out = fp16(X @ W^T + b), [B,NH,S,DH];
// Q scaled by log2e/8. BM=128, BN=128, BK=32; 8 warps (2m x 4n).
// 3-buffer cp.async pipeline; smem-staged coalesced epilogue (STG.128).
// ---------------------------------------------------------------------------
#define GS 80                 // smem row stride bytes (32 f16 = 64 B + 16 pad)
#define GBUF 20480            // per-buffer span (X 10240 + W 10240)
#define G_SMEM 61440
#define EST 272               // epilogue stage row stride bytes (256 + 16 pad)

__global__ __launch_bounds__(256, 2) void qkv_hmma(
    const float* __restrict__ bq, const float* __restrict__ bk_,
    const float* __restrict__ bv)
{
    extern __shared__ char smem[];
    const uint32_t sb = smem_u32(smem);
    const int tid  = threadIdx.x;
    const int lane = tid & 31;
    const int wid  = tid >> 5;
    const int wm   = wid >> 2;        // 0..1
    const int wn   = wid & 3;         // 0..3
    const int z    = blockIdx.z;
    const int m0   = blockIdx.y * 128;
    const int n0   = blockIdx.x * 128;

    const __half* xh = g_xh;
    const __half* wh = g_wh[z];
    const float* bias = (z == 0) ? bq : (z == 1) ? bk_ : bv;
    __half* oh = (z == 0) ? g_qh : (z == 1) ? g_kh : g_vh;

    auto issue_copy = [&](int buf, int k0) {
        const uint32_t bb = sb + buf * GBUF;
        #pragma unroll
        for (int u = 0; u < 2; u++) {
            const int chunk = tid*2 + u;       // 0..511
            const int row = chunk >> 2, c16 = chunk & 3;
            const uint32_t so = (uint32_t)(row*GS + c16*16);
            CPASYNC(bb + so,         (const char*)(xh + (size_t)(m0+row)*H_ + k0 + c16*8));
            CPASYNC(bb + 10240 + so, (const char*)(wh + (size_t)(n0+row)*H_ + k0 + c16*8));
        }
        CPCOMMIT();
    };

    float c[4][4][4];
    uint32_t ch[4][4][2];
    #pragma unroll
    for (int mi = 0; mi < 4; mi++)
        #pragma unroll
        for (int ni = 0; ni < 4; ni++) {
            #pragma unroll
            for (int e = 0; e < 4; e++) c[mi][ni][e] = 0.f;
            ch[mi][ni][0] = 0u; ch[mi][ni][1] = 0u;
        }

    issue_copy(0, 0);
    issue_copy(1, 32);

    const int la = lane & 15;
    const int NSTEP = H_ / 32;                 // 32
    int bsel = 0;
    for (int t = 0; t < NSTEP; t++) {
        if (t + 1 < NSTEP) { CPWAIT(1); } else { CPWAIT(0); }
        __syncthreads();                        // copies of tile t visible; tile t-1 reads done
        if (t + 2 < NSTEP) issue_copy((bsel + 2 >= 3) ? bsel - 1 : bsel + 2, (t+2)*32);

        const uint32_t xh_b = sb + bsel * GBUF;
        const uint32_t wh_b = xh_b + 10240;
        #pragma unroll
        for (int kk = 0; kk < 2; kk++) {
            uint32_t Ah[4][4], Bh[2][4];
            #pragma unroll
            for (int mi = 0; mi < 4; mi++) {
                const uint32_t ao = (uint32_t)((wm*64 + mi*16 + la)*GS + kk*32 + (lane>>4)*16);
                ldsm_x4(Ah[mi], xh_b + ao);
            }
            #pragma unroll
            for (int ni2 = 0; ni2 < 2; ni2++) {
                const uint32_t bo = (uint32_t)((wn*32 + ni2*16 + ((lane>>4)<<3) + (lane & 7))*GS
                                               + kk*32 + ((lane>>3)&1)*16);
                ldsm_x4(Bh[ni2], wh_b + bo);
            }
            #pragma unroll
            for (int mi = 0; mi < 4; mi++)
                #pragma unroll
                for (int ni2 = 0; ni2 < 2; ni2++) {
                    mma16816h(ch[mi][2*ni2],     Ah[mi], Bh[ni2]);
                    mma16816h(ch[mi][2*ni2 + 1], Ah[mi], Bh[ni2] + 2);
                }
        }
        // promote fp16 partials to fp32 every k=64 (2 k-steps)
        if (t & 1) {
            #pragma unroll
            for (int mi = 0; mi < 4; mi++)
                #pragma unroll
                for (int ni = 0; ni < 4; ni++) {
                    float2 f0 = h2f2(ch[mi][ni][0]);
                    float2 f1 = h2f2(ch[mi][ni][1]);
                    c[mi][ni][0] += f0.x; c[mi][ni][1] += f0.y;
                    c[mi][ni][2] += f1.x; c[mi][ni][3] += f1.y;
                    ch[mi][ni][0] = 0u; ch[mi][ni][1] = 0u;
                }
        }
        bsel = (bsel + 1 >= 3) ? 0 : bsel + 1;
    }

    // ---- epilogue: +bias, (scale if Q), pack, stage in smem, STG.128 ----
    __syncthreads();                            // all mainloop smem reads done
    const float sc = (z == 0) ? SCALE_Q : 1.f;
    #pragma unroll
    for (int ni = 0; ni < 4; ni++) {
        const int nbcol = wn*32 + ni*8 + (lane & 3)*2;
        const float b0 = bias[n0 + nbcol], b1 = bias[n0 + nbcol + 1];
        #pragma unroll
        for (int mi = 0; mi < 4; mi++) {
            #pragma unroll
            for (int half = 0; half < 2; half++) {
                const int rl = wm*64 + mi*16 + (lane >> 2) + half*8;
                float v0 = (c[mi][ni][half*2 + 0] + b0) * sc;
                float v1 = (c[mi][ni][half*2 + 1] + b1) * sc;
                *(uint32_t*)(smem + rl*EST + nbcol*2) = pack2(v0, v1);
            }
        }
    }
    __syncthreads();
    #pragma unroll
    for (int pass = 0; pass < 8; pass++) {
        const int idx = pass*256 + tid;         // 0..2047
        const int r = idx >> 4;                 // 0..127
        const int ck = idx & 15;                // 16B chunk within row
        uint4 v = *(const uint4*)(smem + r*EST + ck*16);
        const int gr = m0 + r;
        const int bI = gr >> 11, s = gr & (S_ - 1);
        const int hh = (n0 >> 6) + (ck >> 3);
        const int d  = (ck & 7) * 8;
        *(uint4*)(oh + (((size_t)(bI*NH_ + hh))*S_ + s)*DH_ + d) = v;
    }
}

// ---------------------------------------------------------------------------
// mma.sync fp16 dual-branch flash attention.
// QK^T: fp16-accumulate HMMA (2x rate); scores in f16x2 log2-units.
// Softmax fully in f16x2; D-frags ARE the PV A-frags (no packing).
// PV: fp16-accumulate HMMA (2x rate) with per-tile fp32 promotion
//     (tile partial magnitude ~4 vs total ~22 -> rel err ~2e-4).
// 128 threads = 4 warps, 64 q-rows per CTA; 3 CTAs/SM; 3-buffer cp.async K/V.
// ---------------------------------------------------------------------------
#define EA_OFF 0              // 1024 u32 (f16x2 ea pairs) = 4096 B
#define QH_OFF 8192           // 64*144 = 9216
#define KV_OFF 17408
#define KVB    18432          // per-buffer span (K 9216 + V 9216)
#define VH_O   9216
#define SM_BYTES (KV_OFF + 3*KVB)   // 72704
#define RSTRIDE 144           // 64 f16 = 128 B + 16 pad

__global__ __launch_bounds__(128, 3) void attn_mma(
    const float* __restrict__ amask, const float* __restrict__ gate,
    float* __restrict__ out)
{
    extern __shared__ char smem[];
    const uint32_t sb = smem_u32(smem);
    uint32_t* ea_u = (uint32_t*)smem;

    const int tid  = threadIdx.x;
    const int lane = tid & 31;
    const int h  = blockIdx.x;
    const int qt = blockIdx.y;        // 64-row q tile
    const int b  = blockIdx.z;
    const size_t base = ((size_t)(b*NH_ + h)) * S_ * DH_;

    // ---- ea = exp(amask) packed f16x2 per column pair ----
    #pragma unroll
    for (int i = 0; i < 8; i++) {
        const int idx = tid + 128*i;           // 0..1023 pair index
        float e0 = __expf(amask[b*S_ + 2*idx]);
        float e1 = __expf(amask[b*S_ + 2*idx + 1]);
        ea_u[idx] = pack2(e0, e1);
    }

    // ---- Q tile -> smem (pre-scaled fp16) ----
    #pragma unroll
    for (int u = 0; u < 4; u++) {
        const int idx = tid*4 + u;             // 0..511
        const int row = idx >> 3, c16 = idx & 7;
        uint4 v = *(const uint4*)(g_qh + base + (size_t)(qt*64 + row)*DH_ + c16*8);
        *(uint4*)(smem + QH_OFF + row*RSTRIDE + c16*16) = v;
    }

    // ---- K/V async copy ----
    auto issue_kv = [&](int buf, int kt) {
        const uint32_t bb = sb + KV_OFF + buf*KVB;
        #pragma unroll
        for (int u = 0; u < 4; u++) {
            const int chunk = tid*4 + u;       // 0..511
            const int row = chunk >> 3, c16 = chunk & 7;
            const uint32_t so = (uint32_t)(row*RSTRIDE + c16*16);
            const size_t go = base + (size_t)(kt + row)*DH_ + c16*8;
            CPASYNC(bb + so,        (const char*)(g_kh + go));
            CPASYNC(bb + VH_O + so, (const char*)(g_vh + go));
        }
        CPCOMMIT();
    };

    // per-thread fragment coordinates
    const int qr0 = (tid >> 5) * 16;
    const int qrowLo = qt*64 + qr0 + (lane >> 2);
    const unsigned long long* pmLo = g_lm + ((size_t)b*S_ + qrowLo)*32;
    const unsigned long long* pmHi = pmLo + 8*32;
    const int shb = (lane & 3) * 2;            // bit offset within 8-bit nb group

    float cg[8][4], cl[8][4];
    #pragma unroll
    for (int nb = 0; nb < 8; nb++)
        #pragma unroll
        for (int e = 0; e < 4; e++) { cg[nb][e] = 0.f; cl[nb][e] = 0.f; }
    float lg0 = 0.f, lg1 = 0.f, ll0 = 0.f, ll1 = 0.f;

    issue_kv(0, 0);
    issue_kv(1, 64);

    const int la = lane & 15;
    const int NT = S_ / 64;                    // 32
    int bsel = 0;
    for (int t = 0; t < NT; t++) {
        const int kt = t * 64;
        if (t + 1 < NT) { CPWAIT(1); } else { CPWAIT(0); }
        __syncthreads();                        // tile t visible; tile t-1 reads done
        if (t + 2 < NT) issue_kv((bsel + 2 >= 3) ? bsel - 1 : bsel + 2, kt + 128);

        const uint32_t kh_b = sb + KV_OFF + bsel*KVB;
        const uint32_t vh_b = kh_b + VH_O;

        // ---- bit-packed local mask for this tile (2 LDG.64) ----
        const unsigned long long mb64Lo = pmLo[t];
        const unsigned long long mb64Hi = pmHi[t];
        const uint32_t mLo0 = (uint32_t)mb64Lo, mLo1 = (uint32_t)(mb64Lo >> 32);
        const uint32_t mHi0 = (uint32_t)mb64Hi, mHi1 = (uint32_t)(mb64Hi >> 32);

        // ---- QK^T: fp16-accumulate (2x rate), paired x4 ldmatrix for K ----
        uint32_t sp[8][2];
        #pragma unroll
        for (int nb = 0; nb < 8; nb++) { sp[nb][0] = 0u; sp[nb][1] = 0u; }

        #pragma unroll
        for (int kb = 0; kb < 4; kb++) {
            uint32_t aqh[4];
            const uint32_t qaddr = (uint32_t)((qr0 + la)*RSTRIDE + kb*32 + (lane >> 4)*16);
            ldsm_x4(aqh, sb + QH_OFF + qaddr);
            #pragma unroll
            for (int nb2 = 0; nb2 < 4; nb2++) {
                uint32_t b4[4];
                const uint32_t kaddr = (uint32_t)((nb2*16 + ((lane>>4)<<3) + (lane & 7))*RSTRIDE
                                                  + kb*32 + ((lane>>3)&1)*16);
                ldsm_x4(b4, kh_b + kaddr);
                mma16816h(sp[2*nb2],     aqh, b4);
                mma16816h(sp[2*nb2 + 1], aqh, b4 + 2);
            }
        }

        // ---- f16x2 softmax: p = 2^s; pg = p*ea; pl = p & mask ----
        uint32_t apg[4][4], apl[4][4];
        uint32_t sgLo = 0u, sgHi = 0u, slLo = 0u, slHi = 0u;
        #pragma unroll
        for (int nb = 0; nb < 8; nb++) {
            const int cp = ((kt + nb*8) >> 1) + (lane & 3);
            const uint32_t eah = ea_u[cp];
            uint32_t p0 = hex2(sp[nb][0]);         // rows r, cols (c, c+1)
            uint32_t p1 = hex2(sp[nb][1]);         // rows r+8
            uint32_t g0 = hmul2(p0, eah);
            uint32_t g1 = hmul2(p1, eah);
            const uint32_t wLo = (nb < 4) ? mLo0 : mLo1;
            const uint32_t wHi = (nb < 4) ? mHi0 : mHi1;
            const int sh = (nb & 3)*8 + shb;
            const uint32_t tLo = ((wLo >> sh) & 1u) | (((wLo >> sh) & 2u) << 15);
            const uint32_t tHi = ((wHi >> sh) & 1u) | (((wHi >> sh) & 2u) << 15);
            uint32_t l0 = p0 & (tLo * 0xFFFFu);
            uint32_t l1 = p1 & (tHi * 0xFFFFu);
            sgLo = hadd2(sgLo, g0); sgHi = hadd2(sgHi, g1);
            slLo = hadd2(slLo, l0); slHi = hadd2(slHi, l1);
            const int kb = nb >> 1, hf = (nb & 1) * 2;
            apg[kb][hf+0] = g0; apg[kb][hf+1] = g1;
            apl[kb][hf+0] = l0; apl[kb][hf+1] = l1;
        }
        { float2 f;
          f = h2f2(sgLo); lg0 += f.x + f.y;
          f = h2f2(sgHi); lg1 += f.x + f.y;
          f = h2f2(slLo); ll0 += f.x + f.y;
          f = h2f2(slHi); ll1 += f.x + f.y; }

        // ---- PV: fp16-accumulate (2x rate), per-tile fp32 promotion ----
        uint32_t cgh[8][2], clh[8][2];
        #pragma unroll
        for (int nb = 0; nb < 8; nb++) {
            cgh[nb][0] = 0u; cgh[nb][1] = 0u;
            clh[nb][0] = 0u; clh[nb][1] = 0u;
        }
        #pragma unroll
        for (int kb = 0; kb < 4; kb++) {
            #pragma unroll
            for (int nb2 = 0; nb2 < 4; nb2++) {
                uint32_t v4[4];
                const uint32_t vaddr = (uint32_t)((kb*16 + ((lane>>3)&1)*8 + (lane & 7))*RSTRIDE
                                                  + nb2*32 + (lane >> 4)*16);
                ldsm_x4t(v4, vh_b + vaddr);
                mma16816h(cgh[2*nb2],     apg[kb], v4);
                mma16816h(clh[2*nb2],     apl[kb], v4);
                mma16816h(cgh[2*nb2 + 1], apg[kb], v4 + 2);
                mma16816h(clh[2*nb2 + 1], apl[kb], v4 + 2);
            }
        }
        #pragma unroll
        for (int nb = 0; nb < 8; nb++) {
            float2 f0 = h2f2(cgh[nb][0]), f1 = h2f2(cgh[nb][1]);
            cg[nb][0] += f0.x; cg[nb][1] += f0.y;
            cg[nb][2] += f1.x; cg[nb][3] += f1.y;
            float2 e0 = h2f2(clh[nb][0]), e1 = h2f2(clh[nb][1]);
            cl[nb][0] += e0.x; cl[nb][1] += e0.y;
            cl[nb][2] += e1.x; cl[nb][3] += e1.y;
        }
        bsel = (bsel + 1 >= 3) ? 0 : bsel + 1;
    }

    // ---- row-sum reduction across quad ----
    lg0 += __shfl_xor_sync(0xffffffffu, lg0, 1); lg0 += __shfl_xor_sync(0xffffffffu, lg0, 2);
    lg1 += __shfl_xor_sync(0xffffffffu, lg1, 1); lg1 += __shfl_xor_sync(0xffffffffu, lg1, 2);
    ll0 += __shfl_xor_sync(0xffffffffu, ll0, 1); ll0 += __shfl_xor_sync(0xffffffffu, ll0, 2);
    ll1 += __shfl_xor_sync(0xffffffffu, ll1, 1); ll1 += __shfl_xor_sync(0xffffffffu, ll1, 2);

    // ---- gate + writeout ----
    const float gLo = gate[((size_t)(b*NH_ + h))*S_ + qrowLo];
    const float gHi = gate[((size_t)(b*NH_ + h))*S_ + qrowLo + 8];
    const float igLo = (1.f - gLo) / lg0, ilLo = gLo / ll0;
    const float igHi = (1.f - gHi) / lg1, ilHi = gHi / ll1;
    float* oLo = out + ((size_t)(b*S_ + qrowLo))*H_ + h*DH_ + (lane & 3)*2;
    float* oHi = oLo + 8*H_;
    #pragma unroll
    for (int nb = 0; nb < 8; nb++) {
        float2 a, c2;
        a.x  = cl[nb][0]*ilLo + cg[nb][0]*igLo;
        a.y  = cl[nb][1]*ilLo + cg[nb][1]*igLo;
        c2.x = cl[nb][2]*ilHi + cg[nb][2]*igHi;
        c2.y = cl[nb][3]*ilHi + cg[nb][3]*igHi;
        *(float2*)(oLo + nb*8) = a;
        *(float2*)(oHi + nb*8) = c2;
    }
}

// ---------------------------------------------------------------------------
extern "C" void kernel_launch(void* const* d_in, const int* in_sizes, int n_in,
                              void* d_out, int out_size)
{
    const float* X     = (const float*)d_in[0];
    const float* amask = (const float*)d_in[1];
    const int*   lmask = (const int*)  d_in[2];
    const float* gate  = (const float*)d_in[3];
    const float* Wq    = (const float*)d_in[4];
    const float* bq    = (const float*)d_in[5];
    const float* Wk    = (const float*)d_in[6];
    const float* bk    = (const float*)d_in[7];
    const float* Wv    = (const float*)d_in[8];
    const float* bv    = (const float*)d_in[9];
    float* out = (float*)d_out;

    // 1) mask bit-pack + fp16 converts (one launch)
    prep<<<MBLK + (XN4 + 3*WN4)/256, 256>>>(
        lmask, (const float4*)X, (const float4*)Wq, (const float4*)Wk, (const float4*)Wv);

    // 2) QKV projection on tensor cores -> fp16 q/k/v
    cudaFuncSetAttribute(qkv_hmma, cudaFuncAttributeMaxDynamicSharedMemorySize, G_SMEM);
    dim3 g1(H_/128, (B_*S_)/128, 3);
    qkv_hmma<<<g1, 256, G_SMEM>>>(bq, bk, bv);

    // 3) dual-branch attention
    cudaFuncSetAttribute(attn_mma, cudaFuncAttributeMaxDynamicSharedMemorySize, SM_BYTES);
    dim3 g2(NH_, S_/64, B_);
    attn_mma<<<g2, 128, SM_BYTES>>>(amask, gate, out);
}

// round 12
// speedup vs baseline: 1.1605x; 1.1605x over previous
#include <cuda_runtime.h>
#include <cuda_fp16.h>
#include <math.h>
#include <stdint.h>

// Inputs:
// 0 hidden_states f32 [2,2048,1024]
// 1 attention_mask f32 [2,1,1,2048]
// 2 local_attention_mask i32 [2,1,2048,2048]
// 3 gate_outputs f32 [2,16,2048,1]
// 4 Wq 5 bq 6 Wk 7 bk 8 Wv 9 bv
// out f32 [2,2048,1024]

#define B_  2
#define S_  2048
#define H_  1024
#define NH_ 16
#define DH_ 64
#define SCALE_Q 0.18033688011112042f   // 0.125 * log2(e)

// fp16 scratch (device globals; no allocation allowed)
__device__ __half g_xh[(size_t)B_*S_*H_];
__device__ __half g_wh[3][(size_t)H_*H_];
__device__ __half g_qh[(size_t)B_*NH_*S_*DH_];
__device__ __half g_kh[(size_t)B_*NH_*S_*DH_];
__device__ __half g_vh[(size_t)B_*NH_*S_*DH_];
__device__ unsigned long long g_lm[(size_t)B_*S_*32];   // bit-packed local mask

// ===================== helpers =====================
__device__ __forceinline__ uint32_t smem_u32(const void* p) {
    uint32_t a;
    asm("{ .reg .u64 t; cvta.to.shared.u64 t, %1; cvt.u32.u64 %0, t; }" : "=r"(a) : "l"(p));
    return a;
}
// pack two f32 -> f16x2 (lo=a, hi=b)
__device__ __forceinline__ uint32_t pack2(float a, float b) {
    uint32_t h;
    asm("cvt.rn.f16x2.f32 %0, %1, %2;" : "=r"(h) : "f"(b), "f"(a));
    return h;
}
__device__ __forceinline__ uint32_t hex2(uint32_t x) {
    uint32_t y; asm("ex2.approx.f16x2 %0, %1;" : "=r"(y) : "r"(x)); return y;
}
__device__ __forceinline__ uint32_t hmul2(uint32_t a, uint32_t b) {
    uint32_t d; asm("mul.f16x2 %0, %1, %2;" : "=r"(d) : "r"(a), "r"(b)); return d;
}
__device__ __forceinline__ uint32_t hadd2(uint32_t a, uint32_t b) {
    uint32_t d; asm("add.f16x2 %0, %1, %2;" : "=r"(d) : "r"(a), "r"(b)); return d;
}
__device__ __forceinline__ float2 h2f2(uint32_t h) {
    __half2 v = *(__half2*)&h;
    return __half22float2(v);
}
__device__ __forceinline__ void ldsm_x4(uint32_t* r, uint32_t a) {
    asm volatile("ldmatrix.sync.aligned.m8n8.x4.shared.b16 {%0,%1,%2,%3}, [%4];"
        : "=r"(r[0]), "=r"(r[1]), "=r"(r[2]), "=r"(r[3]) : "r"(a));
}
__device__ __forceinline__ void ldsm_x4t(uint32_t* r, uint32_t a) {
    asm volatile("ldmatrix.sync.aligned.m8n8.x4.trans.shared.b16 {%0,%1,%2,%3}, [%4];"
        : "=r"(r[0]), "=r"(r[1]), "=r"(r[2]), "=r"(r[3]) : "r"(a));
}
// fp32-accumulate mma (half rate)
__device__ __forceinline__ void mma16816(float* c, const uint32_t* a, const uint32_t* b) {
    asm volatile("mma.sync.aligned.m16n8k16.row.col.f32.f16.f16.f32 "
        "{%0,%1,%2,%3}, {%4,%5,%6,%7}, {%8,%9}, {%0,%1,%2,%3};"
        : "+f"(c[0]), "+f"(c[1]), "+f"(c[2]), "+f"(c[3])
        : "r"(a[0]), "r"(a[1]), "r"(a[2]), "r"(a[3]), "r"(b[0]), "r"(b[1]));
}
// fp16-accumulate mma (full rate) — D/C are 2 f16x2 regs
__device__ __forceinline__ void mma16816h(uint32_t* c, const uint32_t* a, const uint32_t* b) {
    asm volatile("mma.sync.aligned.m16n8k16.row.col.f16.f16.f16.f16 "
        "{%0,%1}, {%2,%3,%4,%5}, {%6,%7}, {%0,%1};"
        : "+r"(c[0]), "+r"(c[1])
        : "r"(a[0]), "r"(a[1]), "r"(a[2]), "r"(a[3]), "r"(b[0]), "r"(b[1]));
}
#define CPASYNC(dst, src) \
    asm volatile("cp.async.cg.shared.global [%0], [%1], 16;" :: "r"(dst), "l"(src))
#define CPCOMMIT() asm volatile("cp.async.commit_group;" ::: "memory")
#define CPWAIT(n)  asm volatile("cp.async.wait_group %0;" :: "n"(n) : "memory")

// ---------------------------------------------------------------------------
// prep: bit-pack local mask  +  fp32->fp16 convert of X, Wq, Wk, Wv (1 launch)
// ---------------------------------------------------------------------------
#define MBLK 512                       // B_*S_*32 / 256
#define XN4 (B_*S_*H_/4)
#define WN4 (H_*H_/4)
__global__ __launch_bounds__(256) void prep(
    const int* __restrict__ lmask,
    const float4* __restrict__ X,  const float4* __restrict__ Wq,
    const float4* __restrict__ Wk, const float4* __restrict__ Wv)
{
    const int blk = blockIdx.x;
    if (blk < MBLK) {
        const int i = blk * 256 + threadIdx.x;     // 0 .. B*S*32-1
        const int row = i >> 5, seg = i & 31;
        const int4* p = (const int4*)(lmask + ((size_t)row << 11) + seg * 64);
        unsigned long long m = 0ull;
        #pragma unroll
        for (int u = 0; u < 16; u++) {
            int4 v = p[u];
            m |= ((unsigned long long)(v.x != 0)) << (u*4 + 0);
            m |= ((unsigned long long)(v.y != 0)) << (u*4 + 1);
            m |= ((unsigned long long)(v.z != 0)) << (u*4 + 2);
            m |= ((unsigned long long)(v.w != 0)) << (u*4 + 3);
        }
        g_lm[i] = m;
        return;
    }
    int i = (blk - MBLK) * 256 + threadIdx.x;
    const float4* src;
    uint2* dst;
    if (i < XN4)              { src = X;  dst = (uint2*)g_xh;    }
    else if (i < XN4 + WN4)   { src = Wq; dst = (uint2*)g_wh[0]; i -= XN4; }
    else if (i < XN4 + 2*WN4) { src = Wk; dst = (uint2*)g_wh[1]; i -= XN4 + WN4; }
    else                      { src = Wv; dst = (uint2*)g_wh[2]; i -= XN4 + 2*WN4; }
    float4 f = src[i];
    dst[i] = make_uint2(pack2(f.x, f.y), pack2(f.z, f.w));
}

// ---------------------------------------------------------------------------
// QKV projection via fp16 HMMA (fp32 accumulate):  out = fp16(X @ W^T + b),
// [B,NH,S,DH]; Q scaled by log2e/8. BM=128, BN=128, BK=32; 8 warps (2m x 4n).
// 3-buffer cp.async pipeline; smem-staged coalesced epilogue (STG.128).
// ---------------------------------------------------------------------------
#define GS 80                 // smem row stride bytes (32 f16 = 64 B + 16 pad)
#define GBUF 20480            // per-buffer span (X 10240 + W 10240)
#define G_SMEM 61440
#define EST 272               // epilogue stage row stride bytes (256 + 16 pad)

__global__ __launch_bounds__(256, 2) void qkv_hmma(
    const float* __restrict__ bq, const float* __restrict__ bk_,
    const float* __restrict__ bv)
{
    extern __shared__ char smem[];
    const uint32_t sb = smem_u32(smem);
    const int tid  = threadIdx.x;
    const int lane = tid & 31;
    const int wid  = tid >> 5;
    const int wm   = wid >> 2;        // 0..1
    const int wn   = wid & 3;         // 0..3
    const int z    = blockIdx.z;
    const int m0   = blockIdx.y * 128;
    const int n0   = blockIdx.x * 128;

    const __half* xh = g_xh;
    const __half* wh = g_wh[z];
    const float* bias = (z == 0) ? bq : (z == 1) ? bk_ : bv;
    __half* oh = (z == 0) ? g_qh : (z == 1) ? g_kh : g_vh;

    auto issue_copy = [&](int buf, int k0) {
        const uint32_t bb = sb + buf * GBUF;
        #pragma unroll
        for (int u = 0; u < 2; u++) {
            const int chunk = tid*2 + u;       // 0..511
            const int row = chunk >> 2, c16 = chunk & 3;
            const uint32_t so = (uint32_t)(row*GS + c16*16);
            CPASYNC(bb + so,         (const char*)(xh + (size_t)(m0+row)*H_ + k0 + c16*8));
            CPASYNC(bb + 10240 + so, (const char*)(wh + (size_t)(n0+row)*H_ + k0 + c16*8));
        }
        CPCOMMIT();
    };

    float c[4][4][4];
    #pragma unroll
    for (int mi = 0; mi < 4; mi++)
        #pragma unroll
        for (int ni = 0; ni < 4; ni++)
            #pragma unroll
            for (int e = 0; e < 4; e++) c[mi][ni][e] = 0.f;

    issue_copy(0, 0);
    issue_copy(1, 32);

    const int la = lane & 15;
    const int NSTEP = H_ / 32;                 // 32
    int bsel = 0;
    for (int t = 0; t < NSTEP; t++) {
        if (t + 1 < NSTEP) { CPWAIT(1); } else { CPWAIT(0); }
        __syncthreads();                        // copies of tile t visible; tile t-1 reads done
        if (t + 2 < NSTEP) issue_copy((bsel + 2 >= 3) ? bsel - 1 : bsel + 2, (t+2)*32);

        const uint32_t xh_b = sb + bsel * GBUF;
        const uint32_t wh_b = xh_b + 10240;
        #pragma unroll
        for (int kk = 0; kk < 2; kk++) {
            uint32_t Ah[4][4], Bh[2][4];
            #pragma unroll
            for (int mi = 0; mi < 4; mi++) {
                const uint32_t ao = (uint32_t)((wm*64 + mi*16 + la)*GS + kk*32 + (lane>>4)*16);
                ldsm_x4(Ah[mi], xh_b + ao);
            }
            #pragma unroll
            for (int ni2 = 0; ni2 < 2; ni2++) {
                const uint32_t bo = (uint32_t)((wn*32 + ni2*16 + ((lane>>4)<<3) + (lane & 7))*GS
                                               + kk*32 + ((lane>>3)&1)*16);
                ldsm_x4(Bh[ni2], wh_b + bo);
            }
            #pragma unroll
            for (int mi = 0; mi < 4; mi++)
                #pragma unroll
                for (int ni2 = 0; ni2 < 2; ni2++) {
                    mma16816(c[mi][2*ni2],     Ah[mi], Bh[ni2]);
                    mma16816(c[mi][2*ni2 + 1], Ah[mi], Bh[ni2] + 2);
                }
        }
        bsel = (bsel + 1 >= 3) ? 0 : bsel + 1;
    }

    // ---- epilogue: +bias, (scale if Q), pack, stage in smem, STG.128 ----
    __syncthreads();                            // all mainloop smem reads done
    const float sc = (z == 0) ? SCALE_Q : 1.f;
    #pragma unroll
    for (int ni = 0; ni < 4; ni++) {
        const int nbcol = wn*32 + ni*8 + (lane & 3)*2;
        const float b0 = bias[n0 + nbcol], b1 = bias[n0 + nbcol + 1];
        #pragma unroll
        for (int mi = 0; mi < 4; mi++) {
            #pragma unroll
            for (int half = 0; half < 2; half++) {
                const int rl = wm*64 + mi*16 + (lane >> 2) + half*8;
                float v0 = (c[mi][ni][half*2 + 0] + b0) * sc;
                float v1 = (c[mi][ni][half*2 + 1] + b1) * sc;
                *(uint32_t*)(smem + rl*EST + nbcol*2) = pack2(v0, v1);
            }
        }
    }
    __syncthreads();
    #pragma unroll
    for (int pass = 0; pass < 8; pass++) {
        const int idx = pass*256 + tid;         // 0..2047
        const int r = idx >> 4;                 // 0..127
        const int ck = idx & 15;                // 16B chunk within row
        uint4 v = *(const uint4*)(smem + r*EST + ck*16);
        const int gr = m0 + r;
        const int bI = gr >> 11, s = gr & (S_ - 1);
        const int hh = (n0 >> 6) + (ck >> 3);
        const int d  = (ck & 7) * 8;
        *(uint4*)(oh + (((size_t)(bI*NH_ + hh))*S_ + s)*DH_ + d) = v;
    }
}

// ---------------------------------------------------------------------------
// mma.sync fp16 dual-branch flash attention.
// QK^T: fp16-accumulate HMMA (2x rate); scores in f16x2 log2-units.
// Softmax fully in f16x2; D-frags ARE the PV A-frags (no packing).
// PV: fp32-accumulate HMMA.
// Local-mask LDGs hoisted ABOVE the cp.async wait + barrier: their ~250-cyc
// L2 latency is covered by the pipeline drain + QK phase (removes the
// long-scoreboard stall that was serializing each tile).
// 128 threads = 4 warps, 64 q-rows per CTA; 3 CTAs/SM; 3-buffer cp.async K/V.
// ---------------------------------------------------------------------------
#define EA_OFF 0              // 1024 u32 (f16x2 ea pairs) = 4096 B
#define QH_OFF 8192           // 64*144 = 9216
#define KV_OFF 17408
#define KVB    18432          // per-buffer span (K 9216 + V 9216)
#define VH_O   9216
#define SM_BYTES (KV_OFF + 3*KVB)   // 72704
#define RSTRIDE 144           // 64 f16 = 128 B + 16 pad

__global__ __launch_bounds__(128, 3) void attn_mma(
    const float* __restrict__ amask, const float* __restrict__ gate,
    float* __restrict__ out)
{
    extern __shared__ char smem[];
    const uint32_t sb = smem_u32(smem);
    uint32_t* ea_u = (uint32_t*)smem;

    const int tid  = threadIdx.x;
    const int lane = tid & 31;
    const int h  = blockIdx.x;
    const int qt = blockIdx.y;        // 64-row q tile
    const int b  = blockIdx.z;
    const size_t base = ((size_t)(b*NH_ + h)) * S_ * DH_;

    // ---- ea = exp(amask) packed f16x2 per column pair ----
    #pragma unroll
    for (int i = 0; i < 8; i++) {
        const int idx = tid + 128*i;           // 0..1023 pair index
        float e0 = __expf(amask[b*S_ + 2*idx]);
        float e1 = __expf(amask[b*S_ + 2*idx + 1]);
        ea_u[idx] = pack2(e0, e1);
    }

    // ---- Q tile -> smem (pre-scaled fp16) ----
    #pragma unroll
    for (int u = 0; u < 4; u++) {
        const int idx = tid*4 + u;             // 0..511
        const int row = idx >> 3, c16 = idx & 7;
        uint4 v = *(const uint4*)(g_qh + base + (size_t)(qt*64 + row)*DH_ + c16*8);
        *(uint4*)(smem + QH_OFF + row*RSTRIDE + c16*16) = v;
    }

    // ---- K/V async copy ----
    auto issue_kv = [&](int buf, int kt) {
        const uint32_t bb = sb + KV_OFF + buf*KVB;
        #pragma unroll
        for (int u = 0; u < 4; u++) {
            const int chunk = tid*4 + u;       // 0..511
            const int row = chunk >> 3, c16 = chunk & 7;
            const uint32_t so = (uint32_t)(row*RSTRIDE + c16*16);
            const size_t go = base + (size_t)(kt + row)*DH_ + c16*8;
            CPASYNC(bb + so,        (const char*)(g_kh + go));
            CPASYNC(bb + VH_O + so, (const char*)(g_vh + go));
        }
        CPCOMMIT();
    };

    // per-thread fragment coordinates
    const int qr0 = (tid >> 5) * 16;
    const int qrowLo = qt*64 + qr0 + (lane >> 2);
    const unsigned long long* pmLo = g_lm + ((size_t)b*S_ + qrowLo)*32;
    const unsigned long long* pmHi = pmLo + 8*32;
    const int shb = (lane & 3) * 2;            // bit offset within 8-bit nb group

    float cg[8][4], cl[8][4];
    #pragma unroll
    for (int nb = 0; nb < 8; nb++)
        #pragma unroll
        for (int e = 0; e < 4; e++) { cg[nb][e] = 0.f; cl[nb][e] = 0.f; }
    float lg0 = 0.f, lg1 = 0.f, ll0 = 0.f, ll1 = 0.f;

    issue_kv(0, 0);
    issue_kv(1, 64);

    const int la = lane & 15;
    const int NT = S_ / 64;                    // 32
    int bsel = 0;
    for (int t = 0; t < NT; t++) {
        const int kt = t * 64;

        // ---- HOISTED: bit-packed local mask loads (L2) — issue before the
        //      pipeline wait + barrier so their latency is covered by the
        //      drain + QK phase.
        const unsigned long long mb64Lo = pmLo[t];
        const unsigned long long mb64Hi = pmHi[t];

        if (t + 1 < NT) { CPWAIT(1); } else { CPWAIT(0); }
        __syncthreads();                        // tile t visible; tile t-1 reads done
        if (t + 2 < NT) issue_kv((bsel + 2 >= 3) ? bsel - 1 : bsel + 2, kt + 128);

        const uint32_t kh_b = sb + KV_OFF + bsel*KVB;
        const uint32_t vh_b = kh_b + VH_O;

        const uint32_t mLo0 = (uint32_t)mb64Lo, mLo1 = (uint32_t)(mb64Lo >> 32);
        const uint32_t mHi0 = (uint32_t)mb64Hi, mHi1 = (uint32_t)(mb64Hi >> 32);

        // ---- QK^T: fp16-accumulate (2x rate), paired x4 ldmatrix for K ----
        uint32_t sp[8][2];
        #pragma unroll
        for (int nb = 0; nb < 8; nb++) { sp[nb][0] = 0u; sp[nb][1] = 0u; }

        #pragma unroll
        for (int kb = 0; kb < 4; kb++) {
            uint32_t aqh[4];
            const uint32_t qaddr = (uint32_t)((qr0 + la)*RSTRIDE + kb*32 + (lane >> 4)*16);
            ldsm_x4(aqh, sb + QH_OFF + qaddr);
            #pragma unroll
            for (int nb2 = 0; nb2 < 4; nb2++) {
                uint32_t b4[4];
                const uint32_t kaddr = (uint32_t)((nb2*16 + ((lane>>4)<<3) + (lane & 7))*RSTRIDE
                                                  + kb*32 + ((lane>>3)&1)*16);
                ldsm_x4(b4, kh_b + kaddr);
                mma16816h(sp[2*nb2],     aqh, b4);
                mma16816h(sp[2*nb2 + 1], aqh, b4 + 2);
            }
        }

        // ---- f16x2 softmax: p = 2^s; pg = p*ea; pl = p & mask ----
        uint32_t apg[4][4], apl[4][4];
        uint32_t sgLo = 0u, sgHi = 0u, slLo = 0u, slHi = 0u;
        #pragma unroll
        for (int nb = 0; nb < 8; nb++) {
            const int cp = ((kt + nb*8) >> 1) + (lane & 3);
            const uint32_t eah = ea_u[cp];
            uint32_t p0 = hex2(sp[nb][0]);         // rows r, cols (c, c+1)
            uint32_t p1 = hex2(sp[nb][1]);         // rows r+8
            uint32_t g0 = hmul2(p0, eah);
            uint32_t g1 = hmul2(p1, eah);
            const uint32_t wLo = (nb < 4) ? mLo0 : mLo1;
            const uint32_t wHi = (nb < 4) ? mHi0 : mHi1;
            const int sh = (nb & 3)*8 + shb;
            const uint32_t tLo = ((wLo >> sh) & 1u) | (((wLo >> sh) & 2u) << 15);
            const uint32_t tHi = ((wHi >> sh) & 1u) | (((wHi >> sh) & 2u) << 15);
            uint32_t l0 = p0 & (tLo * 0xFFFFu);
            uint32_t l1 = p1 & (tHi * 0xFFFFu);
            sgLo = hadd2(sgLo, g0); sgHi = hadd2(sgHi, g1);
            slLo = hadd2(slLo, l0); slHi = hadd2(slHi, l1);
            const int kb = nb >> 1, hf = (nb & 1) * 2;
            apg[kb][hf+0] = g0; apg[kb][hf+1] = g1;
            apl[kb][hf+0] = l0; apl[kb][hf+1] = l1;
        }
        { float2 f;
          f = h2f2(sgLo); lg0 += f.x + f.y;
          f = h2f2(sgHi); lg1 += f.x + f.y;
          f = h2f2(slLo); ll0 += f.x + f.y;
          f = h2f2(slHi); ll1 += f.x + f.y; }

        // ---- PV: fp32-accumulate, paired x4.trans ldmatrix for V ----
        #pragma unroll
        for (int kb = 0; kb < 4; kb++) {
            #pragma unroll
            for (int nb2 = 0; nb2 < 4; nb2++) {
                uint32_t v4[4];
                const uint32_t vaddr = (uint32_t)((kb*16 + ((lane>>3)&1)*8 + (lane & 7))*RSTRIDE
                                                  + nb2*32 + (lane >> 4)*16);
                ldsm_x4t(v4, vh_b + vaddr);
                mma16816(cg[2*nb2],     apg[kb], v4);
                mma16816(cl[2*nb2],     apl[kb], v4);
                mma16816(cg[2*nb2 + 1], apg[kb], v4 + 2);
                mma16816(cl[2*nb2 + 1], apl[kb], v4 + 2);
            }
        }
        bsel = (bsel + 1 >= 3) ? 0 : bsel + 1;
    }

    // ---- row-sum reduction across quad ----
    lg0 += __shfl_xor_sync(0xffffffffu, lg0, 1); lg0 += __shfl_xor_sync(0xffffffffu, lg0, 2);
    lg1 += __shfl_xor_sync(0xffffffffu, lg1, 1); lg1 += __shfl_xor_sync(0xffffffffu, lg1, 2);
    ll0 += __shfl_xor_sync(0xffffffffu, ll0, 1); ll0 += __shfl_xor_sync(0xffffffffu, ll0, 2);
    ll1 += __shfl_xor_sync(0xffffffffu, ll1, 1); ll1 += __shfl_xor_sync(0xffffffffu, ll1, 2);

    // ---- gate + writeout ----
    const float gLo = gate[((size_t)(b*NH_ + h))*S_ + qrowLo];
    const float gHi = gate[((size_t)(b*NH_ + h))*S_ + qrowLo + 8];
    const float igLo = (1.f - gLo) / lg0, ilLo = gLo / ll0;
    const float igHi = (1.f - gHi) / lg1, ilHi = gHi / ll1;
    float* oLo = out + ((size_t)(b*S_ + qrowLo))*H_ + h*DH_ + (lane & 3)*2;
    float* oHi = oLo + 8*H_;
    #pragma unroll
    for (int nb = 0; nb < 8; nb++) {
        float2 a, c2;
        a.x  = cl[nb][0]*ilLo + cg[nb][0]*igLo;
        a.y  = cl[nb][1]*ilLo + cg[nb][1]*igLo;
        c2.x = cl[nb][2]*ilHi + cg[nb][2]*igHi;
        c2.y = cl[nb][3]*ilHi + cg[nb][3]*igHi;
        *(float2*)(oLo + nb*8) = a;
        *(float2*)(oHi + nb*8) = c2;
    }
}

// ---------------------------------------------------------------------------
extern "C" void kernel_launch(void* const* d_in, const int* in_sizes, int n_in,
                              void* d_out, int out_size)
{
    const float* X     = (const float*)d_in[0];
    const float* amask = (const float*)d_in[1];
    const int*   lmask = (const int*)  d_in[2];
    const float* gate  = (const float*)d_in[3];
    const float* Wq    = (const float*)d_in[4];
    const float* bq    = (const float*)d_in[5];
    const float* Wk    = (const float*)d_in[6];
    const float* bk    = (const float*)d_in[7];
    const float* Wv    = (const float*)d_in[8];
    const float* bv    = (const float*)d_in[9];
    float* out = (float*)d_out;

    // 1) mask bit-pack + fp16 converts (one launch)
    prep<<<MBLK + (XN4 + 3*WN4)/256, 256>>>(
        lmask, (const float4*)X, (const float4*)Wq, (const float4*)Wk, (const float4*)Wv);

    // 2) QKV projection on tensor cores -> fp16 q/k/v
    cudaFuncSetAttribute(qkv_hmma, cudaFuncAttributeMaxDynamicSharedMemorySize, G_SMEM);
    dim3 g1(H_/128, (B_*S_)/128, 3);
    qkv_hmma<<<g1, 256, G_SMEM>>>(bq, bk, bv);

    // 3) dual-branch attention
    cudaFuncSetAttribute(attn_mma, cudaFuncAttributeMaxDynamicSharedMemorySize, SM_BYTES);
    dim3 g2(NH_, S_/64, B_);
    attn_mma<<<g2, 128, SM_BYTES>>>(amask, gate, out);
}